// round 16
// baseline (speedup 1.0000x reference)
#include <cuda_runtime.h>
#include <cuda_bf16.h>
#include <cuda_fp16.h>
#include <math.h>

#define HH 64
#define WW 64
#define HWP 4096
#define BB 4
#define C1 128
#define C2 256
#define NK 9

typedef unsigned int u32;
typedef unsigned long long u64;

// -------- device scratch --------
// g_xp is channel-PAIR interleaved: [b][c/2][pix] float2 = {chan c, chan c+1}
__device__ float g_xp[BB * C2 * HWP];          // (16.8 MB, float2-interleaved)
__device__ float g_off[BB * 2 * NK * HWP];     // offset conv output
__device__ float g_scale[C2];
__device__ float g_bias[C2];
// dcn B tiles (fp16, hi only): 36 chunks x [256 o rows][72 cols]
__device__ __align__(128) __half g_bt[36 * 256 * 72];
// pw B tiles (bf16 split): 2 chunks x [hi|lo] x [256 o rows][72 cols]
__device__ __align__(128) __nv_bfloat16 g_pwt2[2 * 2 * 256 * 72];
// offconv B tiles (fp16, hi only): 36 chunks x [32 rows][72 cols]
__device__ __align__(128) __half g_ow[36 * 32 * 72];

// ======== SMEM layouts (bytes) ========
#define SM_B   0
#define SM_A   73728
#define SM_DYN 147456
#define PW_B   0
#define PW_A   147456
#define PW_DYN 221184
#define OC_B   0
#define OC_A   9216
#define OC_DYN 82944

// -------- PTX helpers (baseline PTX only; tcgen05 is sm_103a-gated and unusable) --------
__device__ __forceinline__ u32 smem_u32(const void* p) {
    u32 a;
    asm("{ .reg .u64 t; cvta.to.shared.u64 t, %1; cvt.u32.u64 %0, t; }" : "=r"(a) : "l"(p));
    return a;
}
__device__ __forceinline__ void cpa16(u32 dst, const void* src) {
    asm volatile("cp.async.cg.shared.global [%0], [%1], 16;" :: "r"(dst), "l"(src));
}
__device__ __forceinline__ void cpa_commit() {
    asm volatile("cp.async.commit_group;" ::: "memory");
}
__device__ __forceinline__ void cpa_wait0() {
    asm volatile("cp.async.wait_group 0;" ::: "memory");
}
__device__ __forceinline__ void cpa_wait1() {
    asm volatile("cp.async.wait_group 1;" ::: "memory");
}
__device__ __forceinline__ void ldsm4(u32* r, u32 addr) {
    asm volatile("ldmatrix.sync.aligned.m8n8.x4.shared.b16 {%0,%1,%2,%3}, [%4];"
                 : "=r"(r[0]), "=r"(r[1]), "=r"(r[2]), "=r"(r[3]) : "r"(addr));
}
__device__ __forceinline__ void mma_bf16(float* d, const u32* a, u32 b0, u32 b1) {
    asm volatile(
        "mma.sync.aligned.m16n8k16.row.col.f32.bf16.bf16.f32 "
        "{%0,%1,%2,%3}, {%4,%5,%6,%7}, {%8,%9}, {%0,%1,%2,%3};"
        : "+f"(d[0]), "+f"(d[1]), "+f"(d[2]), "+f"(d[3])
        : "r"(a[0]), "r"(a[1]), "r"(a[2]), "r"(a[3]), "r"(b0), "r"(b1));
}
__device__ __forceinline__ void mma_f16(float* d, const u32* a, u32 b0, u32 b1) {
    asm volatile(
        "mma.sync.aligned.m16n8k16.row.col.f32.f16.f16.f32 "
        "{%0,%1,%2,%3}, {%4,%5,%6,%7}, {%8,%9}, {%0,%1,%2,%3};"
        : "+f"(d[0]), "+f"(d[1]), "+f"(d[2]), "+f"(d[3])
        : "r"(a[0]), "r"(a[1]), "r"(a[2]), "r"(a[3]), "r"(b0), "r"(b1));
}
__device__ __forceinline__ u32 cvt_bf16x2(float hi_val, float lo_val) {
    u32 r;
    asm("cvt.rn.bf16x2.f32 %0, %1, %2;" : "=r"(r) : "f"(hi_val), "f"(lo_val));
    return r;
}
// bf16 split (pw path)
__device__ __forceinline__ void split2(float v0, float v1, u32& hi, u32& lo) {
    u32 hp = cvt_bf16x2(v1, v0);
    hi = hp;
    float h0 = __uint_as_float(hp << 16);
    float h1 = __uint_as_float(hp & 0xffff0000u);
    lo = cvt_bf16x2(v1 - h1, v0 - h0);
}
// fp16 split (dcn/offconv path)
__device__ __forceinline__ void split2h(float v0, float v1, u32& hi, u32& lo) {
    __half2 h = __floats2half2_rn(v0, v1);
    hi = *(u32*)&h;
    float2 hf = __half22float2(h);
    __half2 l = __floats2half2_rn(v0 - hf.x, v1 - hf.y);
    lo = *(u32*)&l;
}

// ======================= fused prep kernel (single launch) =======================
__global__ void prep_all(const float* __restrict__ gamma, const float* __restrict__ beta,
                         const float* __restrict__ mean, const float* __restrict__ var,
                         const float* __restrict__ pw, const float* __restrict__ dcn,
                         const float* __restrict__ off_w) {
    int bid = blockIdx.x;
    int t = threadIdx.x;   // 0..255
    if (bid < 2) {
        if (bid == 0) {
            float s = gamma[t] * rsqrtf(var[t] + 1e-5f);
            g_scale[t] = s;
            g_bias[t] = beta[t] - mean[t] * s;
        }
        int kc = bid;
        __nv_bfloat16* hi = g_pwt2 + ((size_t)(kc * 2 + 0) * 256 + t) * 72;
        __nv_bfloat16* lo = g_pwt2 + ((size_t)(kc * 2 + 1) * 256 + t) * 72;
#pragma unroll 4
        for (int cl = 0; cl < 64; cl++) {
            float w = pw[t * C1 + kc * 64 + cl];
            __nv_bfloat16 h = __float2bfloat16(w);
            hi[cl] = h;
            lo[cl] = __float2bfloat16(w - __bfloat162float(h));
        }
        for (int cl = 64; cl < 72; cl++) { hi[cl] = __float2bfloat16(0.f); lo[cl] = __float2bfloat16(0.f); }
    } else {
        int chunk = bid - 2;            // 0..35
        int n_ = chunk >> 2, kc = chunk & 3;
        __half* bt = g_bt + ((size_t)chunk * 256 + t) * 72;
#pragma unroll 4
        for (int cl = 0; cl < 64; cl++)
            bt[cl] = __float2half_rn(dcn[(t * C2 + kc * 64 + cl) * NK + n_]);
        for (int cl = 64; cl < 72; cl++) bt[cl] = __float2half_rn(0.f);
        {
            int o = t & 31;
            int grp = t >> 5;
            __half* ow = g_ow + ((size_t)chunk * 32 + o) * 72;
#pragma unroll
            for (int i = 0; i < 8; i++) {
                int cl = grp * 8 + i;
                float w = (o < 18) ? off_w[(o * C2 + kc * 64 + cl) * 9 + n_] : 0.f;
                ow[cl] = __float2half_rn(w);
            }
            if (grp == 0)
                for (int cl = 64; cl < 72; cl++) ow[cl] = __float2half_rn(0.f);
        }
    }
}

// ======================= stage 1: pointwise conv + BN (HMMA bf16 3-pass) =======================
// Epilogue writes channel-pair-interleaved g_xp (float2 per pixel per pair).
__global__ void __launch_bounds__(512, 1) pw_mma_kernel(const float* __restrict__ x) {
    extern __shared__ __align__(16) char smem[];
    u32 sb = smem_u32(smem);

    int t = threadIdx.x;
    int lane = t & 31;
    int warp = t >> 5;
    int rp = blockIdx.x;
    int b = blockIdx.y;

    int m_base = (warp & 3) * 32;
    int n_base = (warp >> 2) * 64;
    u32 aoff = (u32)((m_base + (lane & 7) + ((lane >> 3) & 1) * 8) * 144 + (lane >> 4) * 16);
    u32 boff = (u32)((n_base + (lane & 7) + (lane >> 4) * 8) * 144 + ((lane >> 3) & 1) * 16);

    float acc[2][8][4];
#pragma unroll
    for (int i = 0; i < 2; i++)
#pragma unroll
        for (int j = 0; j < 8; j++)
#pragma unroll
            for (int r = 0; r < 4; r++) acc[i][j][r] = 0.f;

    int m = t & 127;
    int kq = t >> 7;
    int pix = rp * 128 + m;

    {
        const char* src = (const char*)g_pwt2;
        for (int u = t; u < 9216; u += 512)
            cpa16(sb + PW_B + u * 16, src + u * 16);
        cpa_commit();
    }

    const float* xb = x + (size_t)b * C1 * HWP + pix;
#pragma unroll
    for (int kc = 0; kc < 2; kc++) {
        u32 hi[8], lo[8];
#pragma unroll
        for (int j2 = 0; j2 < 8; j2++) {
            float v0 = xb[(size_t)(kc * 64 + kq * 16 + 2 * j2) * HWP];
            float v1 = xb[(size_t)(kc * 64 + kq * 16 + 2 * j2 + 1) * HWP];
            split2(v0, v1, hi[j2], lo[j2]);
        }
        char* ab = smem + PW_A + kc * 36864 + m * 144 + kq * 32;
        *(uint4*)ab = make_uint4(hi[0], hi[1], hi[2], hi[3]);
        *(uint4*)(ab + 16) = make_uint4(hi[4], hi[5], hi[6], hi[7]);
        *(uint4*)(ab + 18432) = make_uint4(lo[0], lo[1], lo[2], lo[3]);
        *(uint4*)(ab + 18432 + 16) = make_uint4(lo[4], lo[5], lo[6], lo[7]);
    }
    cpa_wait0();
    __syncthreads();

#pragma unroll
    for (int kc = 0; kc < 2; kc++) {
        u32 sa = sb + PW_A + kc * 36864;
        u32 sbb = sb + PW_B + kc * 73728;
#pragma unroll
        for (int ks = 0; ks < 4; ks++) {
            u32 ah[2][4], al[2][4];
#pragma unroll
            for (int mt = 0; mt < 2; mt++) {
                ldsm4(ah[mt], sa + aoff + mt * 2304 + ks * 32);
                ldsm4(al[mt], sa + 18432 + aoff + mt * 2304 + ks * 32);
            }
#pragma unroll
            for (int ng = 0; ng < 4; ng++) {
                u32 bh[4], bl[4];
                ldsm4(bh, sbb + boff + ng * 2304 + ks * 32);
                ldsm4(bl, sbb + 36864 + boff + ng * 2304 + ks * 32);
#pragma unroll
                for (int mt = 0; mt < 2; mt++) {
                    mma_bf16(acc[mt][ng * 2 + 0], ah[mt], bh[0], bh[1]);
                    mma_bf16(acc[mt][ng * 2 + 1], ah[mt], bh[2], bh[3]);
                    mma_bf16(acc[mt][ng * 2 + 0], ah[mt], bl[0], bl[1]);
                    mma_bf16(acc[mt][ng * 2 + 1], ah[mt], bl[2], bl[3]);
                    mma_bf16(acc[mt][ng * 2 + 0], al[mt], bh[0], bh[1]);
                    mma_bf16(acc[mt][ng * 2 + 1], al[mt], bh[2], bh[3]);
                }
            }
        }
    }

    // epilogue: BN scale/bias -> g_xp (channel-pair interleaved float2)
    float2* ob = (float2*)g_xp + (size_t)b * 128 * HWP;
#pragma unroll
    for (int mt = 0; mt < 2; mt++) {
#pragma unroll
        for (int j = 0; j < 8; j++) {
            int o2 = (n_base + j * 8) / 2 + (lane & 3);   // channel-pair index
            int o = o2 * 2;
            float s0 = g_scale[o], s1 = g_scale[o + 1];
            float b0 = g_bias[o], b1 = g_bias[o + 1];
            int opix0 = rp * 128 + m_base + mt * 16 + (lane >> 2);
            ob[(size_t)o2 * HWP + opix0] =
                make_float2(acc[mt][j][0] * s0 + b0, acc[mt][j][1] * s1 + b1);
            ob[(size_t)o2 * HWP + opix0 + 8] =
                make_float2(acc[mt][j][2] * s0 + b0, acc[mt][j][3] * s1 + b1);
        }
    }
}

// ======================= stage 2: 3x3 offset conv (HMMA fp16 2-pass) =======================
__global__ void __launch_bounds__(512, 1) offconv_mma_kernel(const float* __restrict__ off_b) {
    extern __shared__ __align__(16) char smem[];
    u32 sb = smem_u32(smem);

    int t = threadIdx.x;
    int lane = t & 31;
    int warp = t >> 5;
    int rp = blockIdx.x;
    int b = blockIdx.y;

    int m_base = (warp & 3) * 32;
    int n_base = (warp >> 2) * 8;
    u32 aoff = (u32)((m_base + (lane & 7) + ((lane >> 3) & 1) * 8) * 144 + (lane >> 4) * 16);
    u32 boff = (u32)((n_base + (lane & 7)) * 144 + (lane >> 3) * 16);

    float acc[2][4];
#pragma unroll
    for (int i = 0; i < 2; i++)
#pragma unroll
        for (int r = 0; r < 4; r++) acc[i][r] = 0.f;

    int m = t & 127;
    int kq = t >> 7;
    int hrow = rp * 2 + (m >> 6);
    int wcol = m & 63;
    const float2* xpb = (const float2*)g_xp + (size_t)b * 128 * HWP;

    auto gather = [&](int cc, int abuf) {
        int n_ = cc >> 2, kc = cc & 3;
        int hs = hrow + (n_ / 3 - 1);
        int ws = wcol + (n_ % 3 - 1);
        bool inb = ((unsigned)hs < 64u) && ((unsigned)ws < 64u);
        const float2* src = xpb + (size_t)((kc * 64 + kq * 16) / 2) * HWP + hs * WW + ws;
        u32 hi[8], lo[8];
#pragma unroll
        for (int j2 = 0; j2 < 8; j2++) {
            float2 v = inb ? src[(size_t)j2 * HWP] : make_float2(0.f, 0.f);
            split2h(v.x, v.y, hi[j2], lo[j2]);
        }
        char* ab = smem + OC_A + abuf * 36864 + m * 144 + kq * 32;
        *(uint4*)ab = make_uint4(hi[0], hi[1], hi[2], hi[3]);
        *(uint4*)(ab + 16) = make_uint4(hi[4], hi[5], hi[6], hi[7]);
        *(uint4*)(ab + 18432) = make_uint4(lo[0], lo[1], lo[2], lo[3]);
        *(uint4*)(ab + 18432 + 16) = make_uint4(lo[4], lo[5], lo[6], lo[7]);
    };

    {
        const char* src = (const char*)g_ow;
        for (int u = t; u < 288; u += 512)
            if (u < 288) cpa16(sb + OC_B + u * 16, src + u * 16);
        cpa_commit();
    }
    gather(0, 0);

    for (int cc = 0; cc < 36; cc++) {
        int abuf = cc & 1;
        __syncthreads();

        if (cc + 1 < 36) {
            const char* src = (const char*)g_ow + (size_t)(cc + 1) * 4608;
            u32 dst = sb + OC_B + ((cc + 1) & 1) * 4608;
            for (int u = t; u < 288; u += 512)
                if (u < 288) cpa16(dst + u * 16, src + u * 16);
        }
        cpa_commit();
        if (cc + 1 < 36) gather(cc + 1, abuf ^ 1);
        cpa_wait1();

        u32 sa = sb + OC_A + abuf * 36864;
        u32 sbb = sb + OC_B + abuf * 4608;
#pragma unroll
        for (int kk = 0; kk < 2; kk++) {
            u32 bh[4];
            ldsm4(bh, sbb + boff + kk * 64);
#pragma unroll
            for (int ksh = 0; ksh < 2; ksh++) {
                int ks = kk * 2 + ksh;
                u32 ah[2][4], al[2][4];
#pragma unroll
                for (int mt = 0; mt < 2; mt++) {
                    ldsm4(ah[mt], sa + aoff + mt * 2304 + ks * 32);
                    ldsm4(al[mt], sa + 18432 + aoff + mt * 2304 + ks * 32);
                }
#pragma unroll
                for (int mt = 0; mt < 2; mt++) {
                    mma_f16(acc[mt], ah[mt], bh[2 * ksh], bh[2 * ksh + 1]);
                    mma_f16(acc[mt], al[mt], bh[2 * ksh], bh[2 * ksh + 1]);
                }
            }
        }
    }

    float* ob = g_off + (size_t)b * 18 * HWP;
#pragma unroll
    for (int mt = 0; mt < 2; mt++) {
#pragma unroll
        for (int r = 0; r < 4; r++) {
            int o = n_base + (lane & 3) * 2 + (r & 1);
            int opix = rp * 128 + m_base + mt * 16 + (lane >> 2) + (r >> 1) * 8;
            if (o < 18)
                ob[(size_t)o * HWP + opix] = acc[mt][r] + off_b[o];
        }
    }
}

// ======================= stage 3: warp-specialized dcn, pipelined producer, LDG.64 gather ====
// 640 threads: warps 0..15 consumers (pure ldsm+mma), warps 16..19 producers (1 thread/pixel).
// Channel-pair interleaved xp: each corner load is one LDG.64 serving 2 channels — halves
// producer LSU/L1 traffic vs fp32-per-channel. Producer software-pipelined in 8 batches
// (4 pairs each) with ping-pong register buffers.
__global__ void __launch_bounds__(640, 1) dcn_mma_kernel(float* __restrict__ out) {
    extern __shared__ __align__(16) char smem[];
    u32 sb = smem_u32(smem);

    int t = threadIdx.x;
    int rp = blockIdx.x;
    int b = blockIdx.y;

    const float2* xpb = (const float2*)g_xp + (size_t)b * 128 * HWP;

    if (t >= 512) {
        // ---------------- producer warps ----------------
        int g = t - 512;                // pixel 0..127
        int pix = rp * 128 + g;
        int hrow = rp * 2 + (g >> 6);
        int pcol = g & 63;
        const float* offb = g_off + (size_t)b * 18 * HWP;

        auto produce = [&](int cc) {
            int n_ = cc >> 2, kc = cc & 3;
            float oy = offb[n_ * HWP + pix];
            float ox = offb[(n_ + 9) * HWP + pix];
            float py = (float)hrow + (float)(n_ / 3 - 1) + oy;
            float px = (float)pcol + (float)(n_ % 3 - 1) + ox;
            py = fminf(fmaxf(py, 0.f), 63.f);
            px = fminf(fmaxf(px, 0.f), 63.f);
            float y0f = floorf(py), x0f = floorf(px);
            int y0 = (int)y0f, x0 = (int)x0f;
            int x1 = min(x0 + 1, 63);
            int y0o = y0 * WW, y1o = min(y0 + 1, 63) * WW;
            float wy = py - y0f, wx = px - x0f;
            float w00 = (1.f - wy) * (1.f - wx);
            float w01 = (1.f - wy) * wx;
            float w10 = wy * (1.f - wx);
            float w11 = wy * wx;

            const float2* plane = xpb + (size_t)(kc * 32) * HWP;   // 32 pairs per chunk
            char* ab = smem + SM_A + (cc & 1) * 36864 + g * 144;

            float2 r0[4][4], r1[4][4];   // [pair][corner]
            // prologue: issue batch 0 (pairs 0..3)
#pragma unroll
            for (int e = 0; e < 4; e++) {
                const float2* q = plane + (size_t)e * HWP;
                r0[e][0] = q[y0o + x0]; r0[e][1] = q[y0o + x1];
                r0[e][2] = q[y1o + x0]; r0[e][3] = q[y1o + x1];
            }
#pragma unroll
            for (int k = 0; k < 8; k++) {
                float2 (*cur)[4] = (k & 1) ? r1 : r0;
                float2 (*nxt)[4] = (k & 1) ? r0 : r1;
                if (k + 1 < 8) {
                    const float2* pn = plane + (size_t)((k + 1) * 4) * HWP;
#pragma unroll
                    for (int e = 0; e < 4; e++) {
                        const float2* q = pn + (size_t)e * HWP;
                        nxt[e][0] = q[y0o + x0]; nxt[e][1] = q[y0o + x1];
                        nxt[e][2] = q[y1o + x0]; nxt[e][3] = q[y1o + x1];
                    }
                }
                u32 h[4], l[4];
#pragma unroll
                for (int e = 0; e < 4; e++) {
                    float v0 = cur[e][0].x * w00 + cur[e][1].x * w01
                             + cur[e][2].x * w10 + cur[e][3].x * w11;
                    float v1 = cur[e][0].y * w00 + cur[e][1].y * w01
                             + cur[e][2].y * w10 + cur[e][3].y * w11;
                    split2h(v0, v1, h[e], l[e]);
                }
                *(uint4*)(ab + k * 16) = make_uint4(h[0], h[1], h[2], h[3]);
                *(uint4*)(ab + 18432 + k * 16) = make_uint4(l[0], l[1], l[2], l[3]);
            }
        };

        // prologue: B(0) + A(0)
        {
            const char* src = (const char*)g_bt;
            for (int u = g; u < 2304; u += 128)
                cpa16(sb + SM_B + u * 16, src + u * 16);
            cpa_commit();
        }
        produce(0);
        cpa_wait0();
        __syncthreads();   // publish A(0)/B(0)

        for (int cc = 0; cc < 36; cc++) {
            if (cc + 1 < 36) {
                const char* srcB = (const char*)g_bt + (size_t)(cc + 1) * 36864;
                u32 dst = sb + SM_B + ((cc + 1) & 1) * 36864;
                for (int u = g; u < 2304; u += 128)
                    cpa16(dst + u * 16, srcB + u * 16);
                cpa_commit();
                produce(cc + 1);
                cpa_wait0();
            }
            __syncthreads();   // publish A(cc+1)/B(cc+1); consumers done with buf cc
        }
        return;
    }

    // ---------------- consumer warps ----------------
    int lane = t & 31;
    int warp = t >> 5;
    int m_base = (warp & 3) * 32;
    int n_base = (warp >> 2) * 64;
    u32 aoff = (u32)((m_base + (lane & 7) + ((lane >> 3) & 1) * 8) * 144 + (lane >> 4) * 16);
    u32 boff = (u32)((n_base + (lane & 7) + (lane >> 4) * 8) * 144 + ((lane >> 3) & 1) * 16);

    float acc[2][8][4];
#pragma unroll
    for (int i = 0; i < 2; i++)
#pragma unroll
        for (int j = 0; j < 8; j++)
#pragma unroll
            for (int r = 0; r < 4; r++) acc[i][j][r] = 0.f;

    __syncthreads();   // wait A(0)/B(0)

    for (int cc = 0; cc < 36; cc++) {
        u32 sa = sb + SM_A + (cc & 1) * 36864;
        u32 sbb = sb + SM_B + (cc & 1) * 36864;
#pragma unroll
        for (int p = 0; p < 4; p++) {
            u32 ah[2][4], al[2][4];
#pragma unroll
            for (int mt = 0; mt < 2; mt++) {
                ldsm4(ah[mt], sa + aoff + mt * 2304 + p * 32);
                ldsm4(al[mt], sa + 18432 + aoff + mt * 2304 + p * 32);
            }
#pragma unroll
            for (int ng = 0; ng < 4; ng++) {
                u32 bh[4];
                ldsm4(bh, sbb + boff + ng * 2304 + p * 32);
#pragma unroll
                for (int mt = 0; mt < 2; mt++) {
                    mma_f16(acc[mt][ng * 2 + 0], ah[mt], bh[0], bh[1]);
                    mma_f16(acc[mt][ng * 2 + 1], ah[mt], bh[2], bh[3]);
                    mma_f16(acc[mt][ng * 2 + 0], al[mt], bh[0], bh[1]);
                    mma_f16(acc[mt][ng * 2 + 1], al[mt], bh[2], bh[3]);
                }
            }
        }
        __syncthreads();   // done with buf cc; producers publish cc+1
    }

    // epilogue: SiLU + store
    float* ob = out + (size_t)b * C2 * HWP;
#pragma unroll
    for (int mt = 0; mt < 2; mt++) {
#pragma unroll
        for (int j = 0; j < 8; j++) {
#pragma unroll
            for (int r = 0; r < 4; r++) {
                int o = n_base + j * 8 + (lane & 3) * 2 + (r & 1);
                int opix = rp * 128 + m_base + mt * 16 + (lane >> 2) + (r >> 1) * 8;
                float f = acc[mt][j][r];
                f = f / (1.f + __expf(-f));
                ob[(size_t)o * HWP + opix] = f;
            }
        }
    }
}

// ======================= launch =======================
extern "C" void kernel_launch(void* const* d_in, const int* in_sizes, int n_in,
                              void* d_out, int out_size) {
    const float* x = (const float*)d_in[0];
    const float* pw_w = (const float*)d_in[1];
    const float* gamma = (const float*)d_in[2];
    const float* beta = (const float*)d_in[3];
    const float* mean = (const float*)d_in[4];
    const float* var = (const float*)d_in[5];
    const float* off_w = (const float*)d_in[6];
    const float* off_b = (const float*)d_in[7];
    const float* dcn_w = (const float*)d_in[8];
    float* out = (float*)d_out;

    (void)in_sizes; (void)n_in; (void)out_size;

    cudaFuncSetAttribute(pw_mma_kernel, cudaFuncAttributeMaxDynamicSharedMemorySize, PW_DYN);
    cudaFuncSetAttribute(offconv_mma_kernel, cudaFuncAttributeMaxDynamicSharedMemorySize, OC_DYN);
    cudaFuncSetAttribute(dcn_mma_kernel, cudaFuncAttributeMaxDynamicSharedMemorySize, SM_DYN);

    prep_all<<<38, 256>>>(gamma, beta, mean, var, pw_w, dcn_w, off_w);
    pw_mma_kernel<<<dim3(32, BB), 512, PW_DYN>>>(x);
    offconv_mma_kernel<<<dim3(32, BB), 512, OC_DYN>>>(off_b);
    dcn_mma_kernel<<<dim3(32, BB), 640, SM_DYN>>>(out);
}

// round 17
// speedup vs baseline: 1.2099x; 1.2099x over previous
#include <cuda_runtime.h>
#include <cuda_bf16.h>
#include <cuda_fp16.h>
#include <math.h>

#define HH 64
#define WW 64
#define HWP 4096
#define BB 4
#define C1 128
#define C2 256
#define NK 9

typedef unsigned int u32;
typedef unsigned long long u64;

// -------- device scratch --------
// g_xp is channel-PAIR interleaved: [b][c/2][pix] float2 = {chan c, chan c+1}
__device__ float g_xp[BB * C2 * HWP];          // (16.8 MB, float2-interleaved)
__device__ float g_off[BB * 2 * NK * HWP];     // offset conv output
__device__ float g_scale[C2];
__device__ float g_bias[C2];
// dcn B tiles (fp16): tile (n,kc) at index n*4+kc: [256 o rows][72 cols]
__device__ __align__(128) __half g_bt[36 * 256 * 72];
// pw B tiles (bf16 split): 2 chunks x [hi|lo] x [256 o rows][72 cols]
__device__ __align__(128) __nv_bfloat16 g_pwt2[2 * 2 * 256 * 72];
// offconv B tiles (fp16): tile (n,kc) at n*4+kc: [32 rows][72 cols]
__device__ __align__(128) __half g_ow[36 * 32 * 72];

// ======== SMEM layouts (bytes) ========
// dcn: B 2 x 36864 | A 2 x 18432 (fp16 hi only)
#define SM_B   0
#define SM_A   73728
#define SM_DYN 110592
// pw: B 2 chunks x 73728 | A 2 bufs x 36864
#define PW_B   0
#define PW_A   147456
#define PW_DYN 221184
// offconv: B 2 bufs x 4608 | A 2 bufs x 18432 (hi only)
#define OC_B   0
#define OC_A   9216
#define OC_DYN 46080

// -------- PTX helpers (baseline PTX only; tcgen05 is sm_103a-gated and unusable) --------
__device__ __forceinline__ u32 smem_u32(const void* p) {
    u32 a;
    asm("{ .reg .u64 t; cvta.to.shared.u64 t, %1; cvt.u32.u64 %0, t; }" : "=r"(a) : "l"(p));
    return a;
}
__device__ __forceinline__ void cpa16(u32 dst, const void* src) {
    asm volatile("cp.async.cg.shared.global [%0], [%1], 16;" :: "r"(dst), "l"(src));
}
__device__ __forceinline__ void cpa_commit() {
    asm volatile("cp.async.commit_group;" ::: "memory");
}
__device__ __forceinline__ void cpa_wait0() {
    asm volatile("cp.async.wait_group 0;" ::: "memory");
}
__device__ __forceinline__ void cpa_wait1() {
    asm volatile("cp.async.wait_group 1;" ::: "memory");
}
__device__ __forceinline__ void ldsm4(u32* r, u32 addr) {
    asm volatile("ldmatrix.sync.aligned.m8n8.x4.shared.b16 {%0,%1,%2,%3}, [%4];"
                 : "=r"(r[0]), "=r"(r[1]), "=r"(r[2]), "=r"(r[3]) : "r"(addr));
}
__device__ __forceinline__ void mma_bf16(float* d, const u32* a, u32 b0, u32 b1) {
    asm volatile(
        "mma.sync.aligned.m16n8k16.row.col.f32.bf16.bf16.f32 "
        "{%0,%1,%2,%3}, {%4,%5,%6,%7}, {%8,%9}, {%0,%1,%2,%3};"
        : "+f"(d[0]), "+f"(d[1]), "+f"(d[2]), "+f"(d[3])
        : "r"(a[0]), "r"(a[1]), "r"(a[2]), "r"(a[3]), "r"(b0), "r"(b1));
}
__device__ __forceinline__ void mma_f16(float* d, const u32* a, u32 b0, u32 b1) {
    asm volatile(
        "mma.sync.aligned.m16n8k16.row.col.f32.f16.f16.f32 "
        "{%0,%1,%2,%3}, {%4,%5,%6,%7}, {%8,%9}, {%0,%1,%2,%3};"
        : "+f"(d[0]), "+f"(d[1]), "+f"(d[2]), "+f"(d[3])
        : "r"(a[0]), "r"(a[1]), "r"(a[2]), "r"(a[3]), "r"(b0), "r"(b1));
}
__device__ __forceinline__ u32 cvt_bf16x2(float hi_val, float lo_val) {
    u32 r;
    asm("cvt.rn.bf16x2.f32 %0, %1, %2;" : "=r"(r) : "f"(hi_val), "f"(lo_val));
    return r;
}
// bf16 split (pw path)
__device__ __forceinline__ void split2(float v0, float v1, u32& hi, u32& lo) {
    u32 hp = cvt_bf16x2(v1, v0);
    hi = hp;
    float h0 = __uint_as_float(hp << 16);
    float h1 = __uint_as_float(hp & 0xffff0000u);
    lo = cvt_bf16x2(v1 - h1, v0 - h0);
}
// single fp16 pack (dcn/offconv path)
__device__ __forceinline__ u32 packh2(float v0, float v1) {
    __half2 h = __floats2half2_rn(v0, v1);
    return *(u32*)&h;
}

// ======================= fused prep kernel (single launch) =======================
__global__ void prep_all(const float* __restrict__ gamma, const float* __restrict__ beta,
                         const float* __restrict__ mean, const float* __restrict__ var,
                         const float* __restrict__ pw, const float* __restrict__ dcn,
                         const float* __restrict__ off_w) {
    int bid = blockIdx.x;
    int t = threadIdx.x;   // 0..255
    if (bid < 2) {
        if (bid == 0) {
            float s = gamma[t] * rsqrtf(var[t] + 1e-5f);
            g_scale[t] = s;
            g_bias[t] = beta[t] - mean[t] * s;
        }
        int kc = bid;
        __nv_bfloat16* hi = g_pwt2 + ((size_t)(kc * 2 + 0) * 256 + t) * 72;
        __nv_bfloat16* lo = g_pwt2 + ((size_t)(kc * 2 + 1) * 256 + t) * 72;
#pragma unroll 4
        for (int cl = 0; cl < 64; cl++) {
            float w = pw[t * C1 + kc * 64 + cl];
            __nv_bfloat16 h = __float2bfloat16(w);
            hi[cl] = h;
            lo[cl] = __float2bfloat16(w - __bfloat162float(h));
        }
        for (int cl = 64; cl < 72; cl++) { hi[cl] = __float2bfloat16(0.f); lo[cl] = __float2bfloat16(0.f); }
    } else {
        int chunk = bid - 2;            // 0..35 = n*4+kc
        int n_ = chunk >> 2, kc = chunk & 3;
        __half* bt = g_bt + ((size_t)chunk * 256 + t) * 72;
#pragma unroll 4
        for (int cl = 0; cl < 64; cl++)
            bt[cl] = __float2half_rn(dcn[(t * C2 + kc * 64 + cl) * NK + n_]);
        for (int cl = 64; cl < 72; cl++) bt[cl] = __float2half_rn(0.f);
        {
            int o = t & 31;
            int grp = t >> 5;
            __half* ow = g_ow + ((size_t)chunk * 32 + o) * 72;
#pragma unroll
            for (int i = 0; i < 8; i++) {
                int cl = grp * 8 + i;
                float w = (o < 18) ? off_w[(o * C2 + kc * 64 + cl) * 9 + n_] : 0.f;
                ow[cl] = __float2half_rn(w);
            }
            if (grp == 0)
                for (int cl = 64; cl < 72; cl++) ow[cl] = __float2half_rn(0.f);
        }
    }
}

// ======================= stage 1: pointwise conv + BN (HMMA bf16 3-pass) =======================
__global__ void __launch_bounds__(512, 1) pw_mma_kernel(const float* __restrict__ x) {
    extern __shared__ __align__(16) char smem[];
    u32 sb = smem_u32(smem);

    int t = threadIdx.x;
    int lane = t & 31;
    int warp = t >> 5;
    int rp = blockIdx.x;
    int b = blockIdx.y;

    int m_base = (warp & 3) * 32;
    int n_base = (warp >> 2) * 64;
    u32 aoff = (u32)((m_base + (lane & 7) + ((lane >> 3) & 1) * 8) * 144 + (lane >> 4) * 16);
    u32 boff = (u32)((n_base + (lane & 7) + (lane >> 4) * 8) * 144 + ((lane >> 3) & 1) * 16);

    float acc[2][8][4];
#pragma unroll
    for (int i = 0; i < 2; i++)
#pragma unroll
        for (int j = 0; j < 8; j++)
#pragma unroll
            for (int r = 0; r < 4; r++) acc[i][j][r] = 0.f;

    int m = t & 127;
    int kq = t >> 7;
    int pix = rp * 128 + m;

    {
        const char* src = (const char*)g_pwt2;
        for (int u = t; u < 9216; u += 512)
            cpa16(sb + PW_B + u * 16, src + u * 16);
        cpa_commit();
    }

    const float* xb = x + (size_t)b * C1 * HWP + pix;
#pragma unroll
    for (int kc = 0; kc < 2; kc++) {
        u32 hi[8], lo[8];
#pragma unroll
        for (int j2 = 0; j2 < 8; j2++) {
            float v0 = xb[(size_t)(kc * 64 + kq * 16 + 2 * j2) * HWP];
            float v1 = xb[(size_t)(kc * 64 + kq * 16 + 2 * j2 + 1) * HWP];
            split2(v0, v1, hi[j2], lo[j2]);
        }
        char* ab = smem + PW_A + kc * 36864 + m * 144 + kq * 32;
        *(uint4*)ab = make_uint4(hi[0], hi[1], hi[2], hi[3]);
        *(uint4*)(ab + 16) = make_uint4(hi[4], hi[5], hi[6], hi[7]);
        *(uint4*)(ab + 18432) = make_uint4(lo[0], lo[1], lo[2], lo[3]);
        *(uint4*)(ab + 18432 + 16) = make_uint4(lo[4], lo[5], lo[6], lo[7]);
    }
    cpa_wait0();
    __syncthreads();

#pragma unroll
    for (int kc = 0; kc < 2; kc++) {
        u32 sa = sb + PW_A + kc * 36864;
        u32 sbb = sb + PW_B + kc * 73728;
#pragma unroll
        for (int ks = 0; ks < 4; ks++) {
            u32 ah[2][4], al[2][4];
#pragma unroll
            for (int mt = 0; mt < 2; mt++) {
                ldsm4(ah[mt], sa + aoff + mt * 2304 + ks * 32);
                ldsm4(al[mt], sa + 18432 + aoff + mt * 2304 + ks * 32);
            }
#pragma unroll
            for (int ng = 0; ng < 4; ng++) {
                u32 bh[4], bl[4];
                ldsm4(bh, sbb + boff + ng * 2304 + ks * 32);
                ldsm4(bl, sbb + 36864 + boff + ng * 2304 + ks * 32);
#pragma unroll
                for (int mt = 0; mt < 2; mt++) {
                    mma_bf16(acc[mt][ng * 2 + 0], ah[mt], bh[0], bh[1]);
                    mma_bf16(acc[mt][ng * 2 + 1], ah[mt], bh[2], bh[3]);
                    mma_bf16(acc[mt][ng * 2 + 0], ah[mt], bl[0], bl[1]);
                    mma_bf16(acc[mt][ng * 2 + 1], ah[mt], bl[2], bl[3]);
                    mma_bf16(acc[mt][ng * 2 + 0], al[mt], bh[0], bh[1]);
                    mma_bf16(acc[mt][ng * 2 + 1], al[mt], bh[2], bh[3]);
                }
            }
        }
    }

    // epilogue: BN scale/bias -> g_xp (channel-pair interleaved float2)
    float2* ob = (float2*)g_xp + (size_t)b * 128 * HWP;
#pragma unroll
    for (int mt = 0; mt < 2; mt++) {
#pragma unroll
        for (int j = 0; j < 8; j++) {
            int o2 = (n_base + j * 8) / 2 + (lane & 3);   // channel-pair index
            int o = o2 * 2;
            float s0 = g_scale[o], s1 = g_scale[o + 1];
            float b0 = g_bias[o], b1 = g_bias[o + 1];
            int opix0 = rp * 128 + m_base + mt * 16 + (lane >> 2);
            ob[(size_t)o2 * HWP + opix0] =
                make_float2(acc[mt][j][0] * s0 + b0, acc[mt][j][1] * s1 + b1);
            ob[(size_t)o2 * HWP + opix0 + 8] =
                make_float2(acc[mt][j][2] * s0 + b0, acc[mt][j][3] * s1 + b1);
        }
    }
}

// ======================= stage 2: 3x3 offset conv (HMMA fp16 single-pass) =======================
__global__ void __launch_bounds__(512, 1) offconv_mma_kernel(const float* __restrict__ off_b) {
    extern __shared__ __align__(16) char smem[];
    u32 sb = smem_u32(smem);

    int t = threadIdx.x;
    int lane = t & 31;
    int warp = t >> 5;
    int rp = blockIdx.x;
    int b = blockIdx.y;

    int m_base = (warp & 3) * 32;
    int n_base = (warp >> 2) * 8;
    u32 aoff = (u32)((m_base + (lane & 7) + ((lane >> 3) & 1) * 8) * 144 + (lane >> 4) * 16);
    u32 boff = (u32)((n_base + (lane & 7)) * 144 + (lane >> 3) * 16);

    float acc[2][4];
#pragma unroll
    for (int i = 0; i < 2; i++)
#pragma unroll
        for (int r = 0; r < 4; r++) acc[i][r] = 0.f;

    int m = t & 127;
    int kq = t >> 7;
    int hrow = rp * 2 + (m >> 6);
    int wcol = m & 63;
    const float2* xpb = (const float2*)g_xp + (size_t)b * 128 * HWP;

    auto gather = [&](int cc, int abuf) {
        int n_ = cc >> 2, kc = cc & 3;
        int hs = hrow + (n_ / 3 - 1);
        int ws = wcol + (n_ % 3 - 1);
        bool inb = ((unsigned)hs < 64u) && ((unsigned)ws < 64u);
        const float2* src = xpb + (size_t)((kc * 64 + kq * 16) / 2) * HWP + hs * WW + ws;
        u32 hi[8];
#pragma unroll
        for (int j2 = 0; j2 < 8; j2++) {
            float2 v = inb ? src[(size_t)j2 * HWP] : make_float2(0.f, 0.f);
            hi[j2] = packh2(v.x, v.y);
        }
        char* ab = smem + OC_A + abuf * 18432 + m * 144 + kq * 32;
        *(uint4*)ab = make_uint4(hi[0], hi[1], hi[2], hi[3]);
        *(uint4*)(ab + 16) = make_uint4(hi[4], hi[5], hi[6], hi[7]);
    };

    {
        const char* src = (const char*)g_ow;
        for (int u = t; u < 288; u += 512)
            if (u < 288) cpa16(sb + OC_B + u * 16, src + u * 16);
        cpa_commit();
    }
    gather(0, 0);

    for (int cc = 0; cc < 36; cc++) {
        int abuf = cc & 1;
        __syncthreads();

        if (cc + 1 < 36) {
            const char* src = (const char*)g_ow + (size_t)(cc + 1) * 4608;
            u32 dst = sb + OC_B + ((cc + 1) & 1) * 4608;
            for (int u = t; u < 288; u += 512)
                if (u < 288) cpa16(dst + u * 16, src + u * 16);
        }
        cpa_commit();
        if (cc + 1 < 36) gather(cc + 1, abuf ^ 1);
        cpa_wait1();

        u32 sa = sb + OC_A + abuf * 18432;
        u32 sbb = sb + OC_B + abuf * 4608;
#pragma unroll
        for (int kk = 0; kk < 2; kk++) {
            u32 bh[4];
            ldsm4(bh, sbb + boff + kk * 64);
#pragma unroll
            for (int ksh = 0; ksh < 2; ksh++) {
                int ks = kk * 2 + ksh;
                u32 ah[2][4];
#pragma unroll
                for (int mt = 0; mt < 2; mt++)
                    ldsm4(ah[mt], sa + aoff + mt * 2304 + ks * 32);
#pragma unroll
                for (int mt = 0; mt < 2; mt++)
                    mma_f16(acc[mt], ah[mt], bh[2 * ksh], bh[2 * ksh + 1]);
            }
        }
    }

    float* ob = g_off + (size_t)b * 18 * HWP;
#pragma unroll
    for (int mt = 0; mt < 2; mt++) {
#pragma unroll
        for (int r = 0; r < 4; r++) {
            int o = n_base + (lane & 3) * 2 + (r & 1);
            int opix = rp * 128 + m_base + mt * 16 + (lane >> 2) + (r >> 1) * 8;
            if (o < 18)
                ob[(size_t)o * HWP + opix] = acc[mt][r] + off_b[o];
        }
    }
}

// ======================= stage 3: warp-specialized dcn, single-pass fp16 =======================
// 640 threads: 16 consumer warps (64 mma/chunk each) + 4 producer warps (1 thread/pixel).
// Chunk order is kc-major (n fastest): the same 32 channel-pair planes feed 9 consecutive
// chunks (taps shift by ±1 px) → gather hits L1. A tile is fp16 hi-only (A-rounding error
// ~= already-accepted B-rounding error; total ~3.6e-4 < 1e-3).
__global__ void __launch_bounds__(640, 1) dcn_mma_kernel(float* __restrict__ out) {
    extern __shared__ __align__(16) char smem[];
    u32 sb = smem_u32(smem);

    int t = threadIdx.x;
    int rp = blockIdx.x;
    int b = blockIdx.y;

    const float2* xpb = (const float2*)g_xp + (size_t)b * 128 * HWP;

    if (t >= 512) {
        // ---------------- producer warps ----------------
        int g = t - 512;                // pixel 0..127
        int pix = rp * 128 + g;
        int hrow = rp * 2 + (g >> 6);
        int pcol = g & 63;
        const float* offb = g_off + (size_t)b * 18 * HWP;

        auto produce = [&](int ccc) {
            int n_ = ccc % 9, kc = ccc / 9;
            float oy = offb[n_ * HWP + pix];
            float ox = offb[(n_ + 9) * HWP + pix];
            float py = (float)hrow + (float)(n_ / 3 - 1) + oy;
            float px = (float)pcol + (float)(n_ % 3 - 1) + ox;
            py = fminf(fmaxf(py, 0.f), 63.f);
            px = fminf(fmaxf(px, 0.f), 63.f);
            float y0f = floorf(py), x0f = floorf(px);
            int y0 = (int)y0f, x0 = (int)x0f;
            int x1 = min(x0 + 1, 63);
            int y0o = y0 * WW, y1o = min(y0 + 1, 63) * WW;
            float wy = py - y0f, wx = px - x0f;
            float w00 = (1.f - wy) * (1.f - wx);
            float w01 = (1.f - wy) * wx;
            float w10 = wy * (1.f - wx);
            float w11 = wy * wx;

            const float2* plane = xpb + (size_t)(kc * 32) * HWP;   // 32 pairs per chunk
            char* ab = smem + SM_A + (ccc & 1) * 18432 + g * 144;

            float2 r0[4][4], r1[4][4];   // [pair][corner]
#pragma unroll
            for (int e = 0; e < 4; e++) {
                const float2* q = plane + (size_t)e * HWP;
                r0[e][0] = q[y0o + x0]; r0[e][1] = q[y0o + x1];
                r0[e][2] = q[y1o + x0]; r0[e][3] = q[y1o + x1];
            }
#pragma unroll
            for (int k = 0; k < 8; k++) {
                float2 (*cur)[4] = (k & 1) ? r1 : r0;
                float2 (*nxt)[4] = (k & 1) ? r0 : r1;
                if (k + 1 < 8) {
                    const float2* pn = plane + (size_t)((k + 1) * 4) * HWP;
#pragma unroll
                    for (int e = 0; e < 4; e++) {
                        const float2* q = pn + (size_t)e * HWP;
                        nxt[e][0] = q[y0o + x0]; nxt[e][1] = q[y0o + x1];
                        nxt[e][2] = q[y1o + x0]; nxt[e][3] = q[y1o + x1];
                    }
                }
                u32 h[4];
#pragma unroll
                for (int e = 0; e < 4; e++) {
                    float v0 = cur[e][0].x * w00 + cur[e][1].x * w01
                             + cur[e][2].x * w10 + cur[e][3].x * w11;
                    float v1 = cur[e][0].y * w00 + cur[e][1].y * w01
                             + cur[e][2].y * w10 + cur[e][3].y * w11;
                    h[e] = packh2(v0, v1);
                }
                *(uint4*)(ab + k * 16) = make_uint4(h[0], h[1], h[2], h[3]);
            }
        };

        // prologue: B(0) (tile n=0,kc=0 = index 0) + A(0)
        {
            const char* src = (const char*)g_bt;
            for (int u = g; u < 2304; u += 128)
                cpa16(sb + SM_B + u * 16, src + u * 16);
            cpa_commit();
        }
        produce(0);
        cpa_wait0();
        __syncthreads();   // publish A(0)/B(0)

        for (int ccc = 0; ccc < 36; ccc++) {
            if (ccc + 1 < 36) {
                int nn = (ccc + 1) % 9, nk = (ccc + 1) / 9;
                const char* srcB = (const char*)g_bt + (size_t)(nn * 4 + nk) * 36864;
                u32 dst = sb + SM_B + ((ccc + 1) & 1) * 36864;
                for (int u = g; u < 2304; u += 128)
                    cpa16(dst + u * 16, srcB + u * 16);
                cpa_commit();
                produce(ccc + 1);
                cpa_wait0();
            }
            __syncthreads();   // publish A/B(ccc+1); consumers done with buf ccc
        }
        return;
    }

    // ---------------- consumer warps ----------------
    int lane = t & 31;
    int warp = t >> 5;
    int m_base = (warp & 3) * 32;
    int n_base = (warp >> 2) * 64;
    u32 aoff = (u32)((m_base + (lane & 7) + ((lane >> 3) & 1) * 8) * 144 + (lane >> 4) * 16);
    u32 boff = (u32)((n_base + (lane & 7) + (lane >> 4) * 8) * 144 + ((lane >> 3) & 1) * 16);

    float acc[2][8][4];
#pragma unroll
    for (int i = 0; i < 2; i++)
#pragma unroll
        for (int j = 0; j < 8; j++)
#pragma unroll
            for (int r = 0; r < 4; r++) acc[i][j][r] = 0.f;

    __syncthreads();   // wait A(0)/B(0)

    for (int ccc = 0; ccc < 36; ccc++) {
        u32 sa = sb + SM_A + (ccc & 1) * 18432;
        u32 sbb = sb + SM_B + (ccc & 1) * 36864;
#pragma unroll
        for (int p = 0; p < 4; p++) {
            u32 ah[2][4];
#pragma unroll
            for (int mt = 0; mt < 2; mt++)
                ldsm4(ah[mt], sa + aoff + mt * 2304 + p * 32);
#pragma unroll
            for (int ng = 0; ng < 4; ng++) {
                u32 bh[4];
                ldsm4(bh, sbb + boff + ng * 2304 + p * 32);
#pragma unroll
                for (int mt = 0; mt < 2; mt++) {
                    mma_f16(acc[mt][ng * 2 + 0], ah[mt], bh[0], bh[1]);
                    mma_f16(acc[mt][ng * 2 + 1], ah[mt], bh[2], bh[3]);
                }
            }
        }
        __syncthreads();   // done with buf ccc; producers publish ccc+1
    }

    // epilogue: SiLU + store
    float* ob = out + (size_t)b * C2 * HWP;
#pragma unroll
    for (int mt = 0; mt < 2; mt++) {
#pragma unroll
        for (int j = 0; j < 8; j++) {
#pragma unroll
            for (int r = 0; r < 4; r++) {
                int o = n_base + j * 8 + (lane & 3) * 2 + (r & 1);
                int opix = rp * 128 + m_base + mt * 16 + (lane >> 2) + (r >> 1) * 8;
                float f = acc[mt][j][r];
                f = f / (1.f + __expf(-f));
                ob[(size_t)o * HWP + opix] = f;
            }
        }
    }
}

// ======================= launch =======================
extern "C" void kernel_launch(void* const* d_in, const int* in_sizes, int n_in,
                              void* d_out, int out_size) {
    const float* x = (const float*)d_in[0];
    const float* pw_w = (const float*)d_in[1];
    const float* gamma = (const float*)d_in[2];
    const float* beta = (const float*)d_in[3];
    const float* mean = (const float*)d_in[4];
    const float* var = (const float*)d_in[5];
    const float* off_w = (const float*)d_in[6];
    const float* off_b = (const float*)d_in[7];
    const float* dcn_w = (const float*)d_in[8];
    float* out = (float*)d_out;

    (void)in_sizes; (void)n_in; (void)out_size;

    cudaFuncSetAttribute(pw_mma_kernel, cudaFuncAttributeMaxDynamicSharedMemorySize, PW_DYN);
    cudaFuncSetAttribute(offconv_mma_kernel, cudaFuncAttributeMaxDynamicSharedMemorySize, OC_DYN);
    cudaFuncSetAttribute(dcn_mma_kernel, cudaFuncAttributeMaxDynamicSharedMemorySize, SM_DYN);

    prep_all<<<38, 256>>>(gamma, beta, mean, var, pw_w, dcn_w, off_w);
    pw_mma_kernel<<<dim3(32, BB), 512, PW_DYN>>>(x);
    offconv_mma_kernel<<<dim3(32, BB), 512, OC_DYN>>>(off_b);
    dcn_mma_kernel<<<dim3(32, BB), 640, SM_DYN>>>(out);
}